// round 11
// baseline (speedup 1.0000x reference)
#include <cuda_runtime.h>
#include <cuda_bf16.h>
#include <cstdint>

#define B_   16
#define C_   64
#define H_   64
#define W_   64
#define N_   4096
#define M_   1024
#define D8   8
#define D2   32
#define CH48 48

// Device scratch (no cudaMalloc allowed)
__device__ float d_tmp[B_ * CH48 * N_];   // only theta (ch 0..7) used
__device__ float d_phi[B_ * D8 * M_];     // pooled phi (f32)
__device__ float d_g[B_ * D2 * M_];       // pooled g   (f32)

// ---- f32x2 packed helpers ---------------------------------------------------
__device__ __forceinline__ void ffma2(unsigned long long& d,
                                      unsigned long long a,
                                      unsigned long long b) {
    asm("fma.rn.f32x2 %0, %1, %2, %0;" : "+l"(d) : "l"(a), "l"(b));
}
__device__ __forceinline__ unsigned long long pack_ff(float lo, float hi) {
    unsigned long long r;
    asm("mov.b64 %0, {%1,%2};" : "=l"(r) : "f"(lo), "f"(hi));
    return r;
}
__device__ __forceinline__ void unpack_ff(unsigned long long v, float& lo, float& hi) {
    asm("mov.b64 {%0,%1}, %2;" : "=f"(lo), "=f"(hi) : "l"(v));
}

// ---- mma wrappers (baseline PTX, legal on plain sm_103) ----------------------
__device__ __forceinline__ void mma16816(float& d0, float& d1, float& d2, float& d3,
                                         uint32_t a0, uint32_t a1, uint32_t a2, uint32_t a3,
                                         uint32_t b0, uint32_t b1) {
    asm volatile(
        "mma.sync.aligned.m16n8k16.row.col.f32.bf16.bf16.f32 "
        "{%0,%1,%2,%3}, {%4,%5,%6,%7}, {%8,%9}, {%0,%1,%2,%3};"
        : "+f"(d0), "+f"(d1), "+f"(d2), "+f"(d3)
        : "r"(a0), "r"(a1), "r"(a2), "r"(a3), "r"(b0), "r"(b1));
}
__device__ __forceinline__ void mma1688_tf32(float& d0, float& d1, float& d2, float& d3,
                                             uint32_t a0, uint32_t a1, uint32_t a2, uint32_t a3,
                                             uint32_t b0, uint32_t b1) {
    asm volatile(
        "mma.sync.aligned.m16n8k8.row.col.f32.tf32.tf32.f32 "
        "{%0,%1,%2,%3}, {%4,%5,%6,%7}, {%8,%9}, {%0,%1,%2,%3};"
        : "+f"(d0), "+f"(d1), "+f"(d2), "+f"(d3)
        : "r"(a0), "r"(a1), "r"(a2), "r"(a3), "r"(b0), "r"(b1));
}
__device__ __forceinline__ uint32_t to_tf32(float v) {
    uint32_t r;
    asm("cvt.rna.tf32.f32 %0, %1;" : "=r"(r) : "f"(v));
    return r;
}
__device__ __forceinline__ uint32_t bf16x2_of(float lo, float hi) {
    uint32_t r;
    asm("cvt.rn.bf16x2.f32 %0, %1, %2;" : "=r"(r) : "f"(hi), "f"(lo));
    return r;
}
__device__ __forceinline__ float ex2f(float v) {
    float r;
    asm("ex2.approx.f32 %0, %1;" : "=f"(r) : "f"(v));
    return r;
}

// ---------------------------------------------------------------------------
// P1: FUSED conv1x1 + 2x2 maxpool (proven)
// ---------------------------------------------------------------------------
__global__ void __launch_bounds__(256) convpool_kernel(
    const float* __restrict__ x,
    const float* __restrict__ w_theta, const float* __restrict__ b_theta,
    const float* __restrict__ w_phi,   const float* __restrict__ b_phi,
    const float* __restrict__ w_g,     const float* __restrict__ b_g)
{
    __shared__ float w_s[C_ * 24];
    __shared__ float bias_s[24];
    int tid    = threadIdx.x;
    int chbase = blockIdx.y * 24;

    for (int i = tid; i < C_ * 24; i += 256) {
        int c = i / 24, chp = i % 24;
        int ch = chbase + chp;
        float v;
        if (ch < 8)       v = w_theta[ch * C_ + c];
        else if (ch < 16) v = w_phi[(ch - 8) * C_ + c];
        else              v = w_g[(ch - 16) * C_ + c];
        w_s[i] = v;
    }
    if (tid < 24) {
        int ch = chbase + tid;
        bias_s[tid] = (ch < 8) ? b_theta[ch]
                    : (ch < 16 ? b_phi[ch - 8] : b_g[ch - 16]);
    }
    __syncthreads();

    int idx = blockIdx.x * 256 + tid;
    int b  = idx >> 10;
    int q  = idx & 1023;
    int mh = q >> 5, mw = q & 31;
    int n00 = (2 * mh) * W_ + 2 * mw;

    unsigned long long accR0[24], accR1[24];
    #pragma unroll
    for (int j = 0; j < 24; j++) {
        unsigned long long bb = pack_ff(bias_s[j], bias_s[j]);
        accR0[j] = bb; accR1[j] = bb;
    }

    const float* xb = x + ((size_t)b * C_) * N_ + n00;
    #pragma unroll 4
    for (int c = 0; c < C_; c++) {
        unsigned long long x0 = *(const unsigned long long*)(xb + (size_t)c * N_);
        unsigned long long x1 = *(const unsigned long long*)(xb + (size_t)c * N_ + W_);
        const float* wrow = w_s + c * 24;
        #pragma unroll
        for (int j = 0; j < 24; j++) {
            float wj = wrow[j];
            unsigned long long w2 = pack_ff(wj, wj);
            ffma2(accR0[j], x0, w2);
            ffma2(accR1[j], x1, w2);
        }
    }

    int m = mh * 32 + mw;
    if (chbase == 0) {
        float* tb = d_tmp + (size_t)b * CH48 * N_ + n00;
        #pragma unroll
        for (int ch = 0; ch < 8; ch++) {
            *(unsigned long long*)(tb + (size_t)ch * N_)      = accR0[ch];
            *(unsigned long long*)(tb + (size_t)ch * N_ + W_) = accR1[ch];
        }
        #pragma unroll
        for (int ch = 8; ch < 16; ch++) {
            float a0, a1, b0, b1;
            unpack_ff(accR0[ch], a0, a1);
            unpack_ff(accR1[ch], b0, b1);
            d_phi[((size_t)b * D8 + (ch - 8)) * M_ + m]
                = fmaxf(fmaxf(a0, a1), fmaxf(b0, b1));
        }
        #pragma unroll
        for (int ch = 16; ch < 24; ch++) {
            float a0, a1, b0, b1;
            unpack_ff(accR0[ch], a0, a1);
            unpack_ff(accR1[ch], b0, b1);
            d_g[((size_t)b * D2 + (ch - 16)) * M_ + m]
                = fmaxf(fmaxf(a0, a1), fmaxf(b0, b1));
        }
    } else {
        #pragma unroll
        for (int chp = 0; chp < 24; chp++) {
            float a0, a1, b0, b1;
            unpack_ff(accR0[chp], a0, a1);
            unpack_ff(accR1[chp], b0, b1);
            d_g[((size_t)b * D2 + 8 + chp) * M_ + m]
                = fmaxf(fmaxf(a0, a1), fmaxf(b0, b1));
        }
    }
}

// ---------------------------------------------------------------------------
// Main kernel: R9/R10 proven structure; this round = instruction-stream diet.
//   - induction pointers (pPhi += 512B, pG += 32B; nt offsets are immediates)
//   - g fragment loads hoisted ahead of the frag chain (independent)
//   - vectorized g setup (float4)
// Layouts identical to R10 (LDS.64 frag slots). Numerics identical.
// ---------------------------------------------------------------------------
#define GS3    2080                         // g row stride bytes (520 words)
#define XSTR   33
#define OFF_G    0                          // 32*2080 = 66560
#define OFF_PHI  66560                      // 1024*32 = 32768 -> 99328
#define OFF_TH   99328                      // 4096  -> 103424
#define OFF_WO   103424                     // 8192  -> 111616
#define OFF_BO   111616                     // 256   -> 111872
#define OFF_RS   111872                     // 1024  -> 112896
#define OFF_AG   0                          // alias G (dead after loop), 18432
#define OFF_XCH  18432                      // alias G, 16896 -> 35328 < 66560
#define SMEM_REQ 112896

__global__ void __launch_bounds__(512, 2) attn_main_kernel(
    const float* __restrict__ x,
    const float* __restrict__ w_o,
    const float* __restrict__ b_o,
    const float* __restrict__ sigma,
    float* __restrict__ out)
{
    extern __shared__ char smp[];
    uint32_t* th_s  = (uint32_t*)(smp + OFF_TH);
    float*    wo_s  = (float*)(smp + OFF_WO);
    float*    bo_s  = (float*)(smp + OFF_BO);
    float*    rs_s  = (float*)(smp + OFF_RS);
    float*    ag_s  = (float*)(smp + OFF_AG);

    int tid   = threadIdx.x;
    int warp  = tid >> 5, lane = tid & 31;
    int b     = blockIdx.y;
    int qbase = blockIdx.x * 128;

    // ---- cooperative loads (packed layouts) ----
    {
        // phi: u64 slot per (n, tg): (k=tg lo, k=tg+4 hi), tf32
        const float* psrc = d_phi + (size_t)b * D8 * M_;
        for (int i = tid; i < D8 * M_; i += 512) {
            int d = i >> 10, m = i & 1023;
            *(uint32_t*)(smp + OFF_PHI + m * 32 + (d & 3) * 8 + (d >> 2) * 4)
                = to_tf32(psrc[i]);
        }
        // g: float4 reads -> 2 bf16x2 frag-slot stores (half the iterations)
        const float* gsrc = d_g + (size_t)b * D2 * M_;
        for (int i = tid; i < D2 * (M_ / 4); i += 512) {
            int c = i >> 8;
            int m = (i & 255) * 4;
            float4 gv = *(const float4*)(gsrc + (size_t)c * M_ + m);
            __nv_bfloat162 h0 = __floats2bfloat162_rn(gv.x, gv.y);
            __nv_bfloat162 h1 = __floats2bfloat162_rn(gv.z, gv.w);
            int r0 = m & 15;
            int r1 = (m + 2) & 15;
            char* base = smp + OFF_G + c * GS3 + (m & ~15) * 2;
            *(uint32_t*)(base + ((r0 >> 1) & 3) * 8 + (r0 >> 3) * 4) = *(uint32_t*)&h0;
            *(uint32_t*)(base + ((r1 >> 1) & 3) * 8 + (r1 >> 3) * 4) = *(uint32_t*)&h1;
        }
        // theta (prescaled by log2e), tf32
        const float* tsrc = d_tmp + (size_t)b * CH48 * N_ + qbase;
        for (int i = tid; i < 1024; i += 512) {
            int d = i >> 7, q = i & 127;
            th_s[q * 8 + d] = to_tf32(tsrc[(size_t)d * N_ + q] * 1.4426950408889634f);
        }
        const float4* w4 = (const float4*)w_o;
        float4* ws4 = (float4*)wo_s;
        for (int i = tid; i < 64 * 32 / 4; i += 512) ws4[i] = w4[i];
        if (tid < 64) bo_s[tid] = b_o[tid];
    }
    __syncthreads();

    int pair = warp >> 1;
    int half = warp & 1;
    int q0   = pair * 16;
    int g    = lane >> 2;
    int tg   = lane & 3;

    uint32_t ta0 = th_s[(q0 + g) * 8 + tg];
    uint32_t ta1 = th_s[(q0 + g + 8) * 8 + tg];
    uint32_t ta2 = th_s[(q0 + g) * 8 + tg + 4];
    uint32_t ta3 = th_s[(q0 + g + 8) * 8 + tg + 4];

    float rs_lo = 0.f, rs_hi = 0.f;
    float acc[4][4];
    #pragma unroll
    for (int nt = 0; nt < 4; nt++)
        #pragma unroll
        for (int r = 0; r < 4; r++) acc[nt][r] = 0.f;

    // induction pointers: all other offsets are compile-time immediates
    const char* pPhi = smp + OFF_PHI + (half * 512 + g) * 32 + tg * 8;
    const char* pG   = smp + OFF_G + g * GS3 + half * 1024 + tg * 8;

    // ---- 32 units of 16 keys ----
    #pragma unroll 1
    for (int u = 0; u < 32; u++) {
        // operand loads first (g loads independent of the frag chain)
        uint2 p0 = *(const uint2*)(pPhi);
        uint2 p1 = *(const uint2*)(pPhi + 256);
        uint2 g0 = *(const uint2*)(pG);
        uint2 g1 = *(const uint2*)(pG + 8 * GS3);
        uint2 g2 = *(const uint2*)(pG + 16 * GS3);
        uint2 g3 = *(const uint2*)(pG + 24 * GS3);
        pPhi += 512;
        pG   += 32;

        float e0 = 0.f, e1 = 0.f, e2 = 0.f, e3 = 0.f;
        mma1688_tf32(e0, e1, e2, e3, ta0, ta1, ta2, ta3, p0.x, p0.y);
        float f0 = 0.f, f1 = 0.f, f2 = 0.f, f3 = 0.f;
        mma1688_tf32(f0, f1, f2, f3, ta0, ta1, ta2, ta3, p1.x, p1.y);

        e0 = ex2f(e0); e1 = ex2f(e1); e2 = ex2f(e2); e3 = ex2f(e3);
        f0 = ex2f(f0); f1 = ex2f(f1); f2 = ex2f(f2); f3 = ex2f(f3);
        rs_lo += (e0 + e1) + (f0 + f1);
        rs_hi += (e2 + e3) + (f2 + f3);

        uint32_t a0 = bf16x2_of(e0, e1);
        uint32_t a1 = bf16x2_of(e2, e3);
        uint32_t a2 = bf16x2_of(f0, f1);
        uint32_t a3 = bf16x2_of(f2, f3);

        mma16816(acc[0][0], acc[0][1], acc[0][2], acc[0][3], a0, a1, a2, a3, g0.x, g0.y);
        mma16816(acc[1][0], acc[1][1], acc[1][2], acc[1][3], a0, a1, a2, a3, g1.x, g1.y);
        mma16816(acc[2][0], acc[2][1], acc[2][2], acc[2][3], a0, a1, a2, a3, g2.x, g2.y);
        mma16816(acc[3][0], acc[3][1], acc[3][2], acc[3][3], a0, a1, a2, a3, g3.x, g3.y);
    }

    // ---- rowsums over quad ----
    rs_lo += __shfl_xor_sync(0xffffffffu, rs_lo, 1);
    rs_lo += __shfl_xor_sync(0xffffffffu, rs_lo, 2);
    rs_hi += __shfl_xor_sync(0xffffffffu, rs_hi, 1);
    rs_hi += __shfl_xor_sync(0xffffffffu, rs_hi, 2);
    if (tg == 0) {
        rs_s[warp * 16 + g]     = rs_lo;
        rs_s[warp * 16 + 8 + g] = rs_hi;
    }
    __syncthreads();   // all G/phi reads done -> AG/XCH aliases now safe

    // ---- pair combine ----
    float* xch = (float*)(smp + OFF_XCH) + pair * (16 * XSTR);
    if (half == 1) {
        #pragma unroll
        for (int nt = 0; nt < 4; nt++) {
            int c0 = nt * 8 + 2 * tg;
            xch[g * XSTR + c0]           = acc[nt][0];
            xch[g * XSTR + c0 + 1]       = acc[nt][1];
            xch[(g + 8) * XSTR + c0]     = acc[nt][2];
            xch[(g + 8) * XSTR + c0 + 1] = acc[nt][3];
        }
    }
    __syncthreads();
    if (half == 0) {
        float inv_lo = 1.f / (rs_s[(2 * pair) * 16 + g]     + rs_s[(2 * pair + 1) * 16 + g]);
        float inv_hi = 1.f / (rs_s[(2 * pair) * 16 + g + 8] + rs_s[(2 * pair + 1) * 16 + g + 8]);
        #pragma unroll
        for (int nt = 0; nt < 4; nt++) {
            int c0 = nt * 8 + 2 * tg;
            ag_s[(q0 + g) * 36 + c0]         = (acc[nt][0] + xch[g * XSTR + c0])           * inv_lo;
            ag_s[(q0 + g) * 36 + c0 + 1]     = (acc[nt][1] + xch[g * XSTR + c0 + 1])       * inv_lo;
            ag_s[(q0 + g + 8) * 36 + c0]     = (acc[nt][2] + xch[(g + 8) * XSTR + c0])     * inv_hi;
            ag_s[(q0 + g + 8) * 36 + c0 + 1] = (acc[nt][3] + xch[(g + 8) * XSTR + c0 + 1]) * inv_hi;
        }
    }
    __syncthreads();

    // ---- projection + residual epilogue (proven) ----
    float sig = sigma[0];
    int nl = tid & 127;
    int kh = tid >> 7;

    float ag[32];
    #pragma unroll
    for (int c4 = 0; c4 < 8; c4++) {
        float4 v = *(const float4*)(ag_s + nl * 36 + 4 * c4);
        ag[4 * c4 + 0] = v.x; ag[4 * c4 + 1] = v.y;
        ag[4 * c4 + 2] = v.z; ag[4 * c4 + 3] = v.w;
    }
    size_t xoff_base = ((size_t)b * C_ + kh * 16) * N_ + qbase + nl;
    #pragma unroll 4
    for (int kk = 0; kk < 16; kk++) {
        int k = kh * 16 + kk;
        float val = bo_s[k];
        const float4* wrow = (const float4*)(wo_s + k * 32);
        #pragma unroll
        for (int c4 = 0; c4 < 8; c4++) {
            float4 w4 = wrow[c4];
            val += w4.x * ag[4 * c4] + w4.y * ag[4 * c4 + 1]
                 + w4.z * ag[4 * c4 + 2] + w4.w * ag[4 * c4 + 3];
        }
        size_t off = xoff_base + (size_t)kk * N_;
        out[off] = x[off] + sig * val;
    }
}

// ---------------------------------------------------------------------------
extern "C" void kernel_launch(void* const* d_in, const int* in_sizes, int n_in,
                              void* d_out, int out_size)
{
    const float* x       = (const float*)d_in[0];
    const float* w_theta = (const float*)d_in[1];
    const float* b_theta = (const float*)d_in[2];
    const float* w_phi   = (const float*)d_in[3];
    const float* b_phi   = (const float*)d_in[4];
    const float* w_g     = (const float*)d_in[5];
    const float* b_g     = (const float*)d_in[6];
    const float* w_o     = (const float*)d_in[7];
    const float* b_o     = (const float*)d_in[8];
    const float* sigma   = (const float*)d_in[9];
    float* out = (float*)d_out;

    convpool_kernel<<<dim3(B_ * 1024 / 256, 2), 256>>>(x, w_theta, b_theta,
                                                       w_phi, b_phi, w_g, b_g);

    cudaFuncSetAttribute(attn_main_kernel,
                         cudaFuncAttributeMaxDynamicSharedMemorySize, SMEM_REQ);
    attn_main_kernel<<<dim3(N_ / 128, B_), 512, SMEM_REQ>>>(x, w_o, b_o, sigma, out);
}

// round 12
// speedup vs baseline: 1.1396x; 1.1396x over previous
#include <cuda_runtime.h>
#include <cuda_bf16.h>
#include <cstdint>

#define B_   16
#define C_   64
#define H_   64
#define W_   64
#define N_   4096
#define M_   1024
#define D8   8
#define D2   32
#define CH48 48

// Device scratch (no cudaMalloc allowed)
__device__ float d_tmp[B_ * CH48 * N_];   // only theta (ch 0..7) used
__device__ float d_phi[B_ * D8 * M_];     // pooled phi (f32)
__device__ float d_g[B_ * D2 * M_];       // pooled g   (f32)

// ---- f32x2 packed helpers ---------------------------------------------------
__device__ __forceinline__ void ffma2(unsigned long long& d,
                                      unsigned long long a,
                                      unsigned long long b) {
    asm("fma.rn.f32x2 %0, %1, %2, %0;" : "+l"(d) : "l"(a), "l"(b));
}
__device__ __forceinline__ unsigned long long pack_ff(float lo, float hi) {
    unsigned long long r;
    asm("mov.b64 %0, {%1,%2};" : "=l"(r) : "f"(lo), "f"(hi));
    return r;
}
__device__ __forceinline__ void unpack_ff(unsigned long long v, float& lo, float& hi) {
    asm("mov.b64 {%0,%1}, %2;" : "=f"(lo), "=f"(hi) : "l"(v));
}

// ---- mma wrappers (baseline PTX, legal on plain sm_103) ----------------------
__device__ __forceinline__ void mma16816(float& d0, float& d1, float& d2, float& d3,
                                         uint32_t a0, uint32_t a1, uint32_t a2, uint32_t a3,
                                         uint32_t b0, uint32_t b1) {
    asm volatile(
        "mma.sync.aligned.m16n8k16.row.col.f32.bf16.bf16.f32 "
        "{%0,%1,%2,%3}, {%4,%5,%6,%7}, {%8,%9}, {%0,%1,%2,%3};"
        : "+f"(d0), "+f"(d1), "+f"(d2), "+f"(d3)
        : "r"(a0), "r"(a1), "r"(a2), "r"(a3), "r"(b0), "r"(b1));
}
__device__ __forceinline__ void mma1688_tf32(float& d0, float& d1, float& d2, float& d3,
                                             uint32_t a0, uint32_t a1, uint32_t a2, uint32_t a3,
                                             uint32_t b0, uint32_t b1) {
    asm volatile(
        "mma.sync.aligned.m16n8k8.row.col.f32.tf32.tf32.f32 "
        "{%0,%1,%2,%3}, {%4,%5,%6,%7}, {%8,%9}, {%0,%1,%2,%3};"
        : "+f"(d0), "+f"(d1), "+f"(d2), "+f"(d3)
        : "r"(a0), "r"(a1), "r"(a2), "r"(a3), "r"(b0), "r"(b1));
}
__device__ __forceinline__ uint32_t to_tf32(float v) {
    uint32_t r;
    asm("cvt.rna.tf32.f32 %0, %1;" : "=r"(r) : "f"(v));
    return r;
}
__device__ __forceinline__ uint32_t bf16x2_of(float lo, float hi) {
    uint32_t r;
    asm("cvt.rn.bf16x2.f32 %0, %1, %2;" : "=r"(r) : "f"(hi), "f"(lo));
    return r;
}
__device__ __forceinline__ float ex2f(float v) {
    float r;
    asm("ex2.approx.f32 %0, %1;" : "=f"(r) : "f"(v));
    return r;
}

// ---------------------------------------------------------------------------
// P1: FUSED conv1x1 + 2x2 maxpool (proven)
// ---------------------------------------------------------------------------
__global__ void __launch_bounds__(256) convpool_kernel(
    const float* __restrict__ x,
    const float* __restrict__ w_theta, const float* __restrict__ b_theta,
    const float* __restrict__ w_phi,   const float* __restrict__ b_phi,
    const float* __restrict__ w_g,     const float* __restrict__ b_g)
{
    __shared__ float w_s[C_ * 24];
    __shared__ float bias_s[24];
    int tid    = threadIdx.x;
    int chbase = blockIdx.y * 24;

    for (int i = tid; i < C_ * 24; i += 256) {
        int c = i / 24, chp = i % 24;
        int ch = chbase + chp;
        float v;
        if (ch < 8)       v = w_theta[ch * C_ + c];
        else if (ch < 16) v = w_phi[(ch - 8) * C_ + c];
        else              v = w_g[(ch - 16) * C_ + c];
        w_s[i] = v;
    }
    if (tid < 24) {
        int ch = chbase + tid;
        bias_s[tid] = (ch < 8) ? b_theta[ch]
                    : (ch < 16 ? b_phi[ch - 8] : b_g[ch - 16]);
    }
    __syncthreads();

    int idx = blockIdx.x * 256 + tid;
    int b  = idx >> 10;
    int q  = idx & 1023;
    int mh = q >> 5, mw = q & 31;
    int n00 = (2 * mh) * W_ + 2 * mw;

    unsigned long long accR0[24], accR1[24];
    #pragma unroll
    for (int j = 0; j < 24; j++) {
        unsigned long long bb = pack_ff(bias_s[j], bias_s[j]);
        accR0[j] = bb; accR1[j] = bb;
    }

    const float* xb = x + ((size_t)b * C_) * N_ + n00;
    #pragma unroll 4
    for (int c = 0; c < C_; c++) {
        unsigned long long x0 = *(const unsigned long long*)(xb + (size_t)c * N_);
        unsigned long long x1 = *(const unsigned long long*)(xb + (size_t)c * N_ + W_);
        const float* wrow = w_s + c * 24;
        #pragma unroll
        for (int j = 0; j < 24; j++) {
            float wj = wrow[j];
            unsigned long long w2 = pack_ff(wj, wj);
            ffma2(accR0[j], x0, w2);
            ffma2(accR1[j], x1, w2);
        }
    }

    int m = mh * 32 + mw;
    if (chbase == 0) {
        float* tb = d_tmp + (size_t)b * CH48 * N_ + n00;
        #pragma unroll
        for (int ch = 0; ch < 8; ch++) {
            *(unsigned long long*)(tb + (size_t)ch * N_)      = accR0[ch];
            *(unsigned long long*)(tb + (size_t)ch * N_ + W_) = accR1[ch];
        }
        #pragma unroll
        for (int ch = 8; ch < 16; ch++) {
            float a0, a1, b0, b1;
            unpack_ff(accR0[ch], a0, a1);
            unpack_ff(accR1[ch], b0, b1);
            d_phi[((size_t)b * D8 + (ch - 8)) * M_ + m]
                = fmaxf(fmaxf(a0, a1), fmaxf(b0, b1));
        }
        #pragma unroll
        for (int ch = 16; ch < 24; ch++) {
            float a0, a1, b0, b1;
            unpack_ff(accR0[ch], a0, a1);
            unpack_ff(accR1[ch], b0, b1);
            d_g[((size_t)b * D2 + (ch - 16)) * M_ + m]
                = fmaxf(fmaxf(a0, a1), fmaxf(b0, b1));
        }
    } else {
        #pragma unroll
        for (int chp = 0; chp < 24; chp++) {
            float a0, a1, b0, b1;
            unpack_ff(accR0[chp], a0, a1);
            unpack_ff(accR1[chp], b0, b1);
            d_g[((size_t)b * D2 + 8 + chp) * M_ + m]
                = fmaxf(fmaxf(a0, a1), fmaxf(b0, b1));
        }
    }
}

// ---------------------------------------------------------------------------
// Main kernel v5: 256-query CTAs. Each warp owns 16 queries x FULL 1024 keys:
//   - g/phi smem setup executed half as often chip-wide (256 vs 512 CTAs)
//   - rowsum complete after a quad shuffle -> acc normalized IN REGISTERS
//   - pair-combine (xch, rs_s) and 2 barriers deleted
//   - theta loaded directly from gmem (4 LDG) -> th_s staging deleted
// Loop body + layouts identical to proven R10 form.
// ---------------------------------------------------------------------------
#define GS3    2080                         // g row stride bytes (520 words)
#define OFF_G    0                          // 32*2080 = 66560
#define OFF_PHI  66560                      // 1024*32 = 32768 -> 99328
#define OFF_WO   99328                      // 8192  -> 107520
#define OFF_BO   107520                     // 256   -> 107776
#define OFF_AG   0                          // alias G (dead after loop): 256*36*4 = 36864
#define SMEM_REQ 107776

__global__ void __launch_bounds__(512, 2) attn_main_kernel(
    const float* __restrict__ x,
    const float* __restrict__ w_o,
    const float* __restrict__ b_o,
    const float* __restrict__ sigma,
    float* __restrict__ out)
{
    extern __shared__ char smp[];
    float* wo_s = (float*)(smp + OFF_WO);
    float* bo_s = (float*)(smp + OFF_BO);
    float* ag_s = (float*)(smp + OFF_AG);

    int tid   = threadIdx.x;
    int warp  = tid >> 5, lane = tid & 31;
    int b     = blockIdx.y;
    int qbase = blockIdx.x * 256;

    int q0 = warp * 16;
    int g  = lane >> 2;
    int tg = lane & 3;

    // theta A-fragments straight from gmem (prescaled by log2e)
    const float* tsrc = d_tmp + (size_t)b * CH48 * N_ + qbase;
    const float sc = 1.4426950408889634f;
    uint32_t ta0 = to_tf32(tsrc[(size_t)tg * N_ + q0 + g] * sc);
    uint32_t ta1 = to_tf32(tsrc[(size_t)tg * N_ + q0 + g + 8] * sc);
    uint32_t ta2 = to_tf32(tsrc[(size_t)(tg + 4) * N_ + q0 + g] * sc);
    uint32_t ta3 = to_tf32(tsrc[(size_t)(tg + 4) * N_ + q0 + g + 8] * sc);

    // ---- cooperative loads (packed layouts, proven) ----
    {
        // phi: u64 slot per (m, tg): (k=tg lo, k=tg+4 hi), tf32
        const float* psrc = d_phi + (size_t)b * D8 * M_;
        for (int i = tid; i < D8 * M_; i += 512) {
            int d = i >> 10, m = i & 1023;
            *(uint32_t*)(smp + OFF_PHI + m * 32 + (d & 3) * 8 + (d >> 2) * 4)
                = to_tf32(psrc[i]);
        }
        // g: float4 reads -> 2 bf16x2 frag-slot stores
        const float* gsrc = d_g + (size_t)b * D2 * M_;
        for (int i = tid; i < D2 * (M_ / 4); i += 512) {
            int c = i >> 8;
            int m = (i & 255) * 4;
            float4 gv = *(const float4*)(gsrc + (size_t)c * M_ + m);
            __nv_bfloat162 h0 = __floats2bfloat162_rn(gv.x, gv.y);
            __nv_bfloat162 h1 = __floats2bfloat162_rn(gv.z, gv.w);
            int r0 = m & 15;
            int r1 = (m + 2) & 15;
            char* base = smp + OFF_G + c * GS3 + (m & ~15) * 2;
            *(uint32_t*)(base + ((r0 >> 1) & 3) * 8 + (r0 >> 3) * 4) = *(uint32_t*)&h0;
            *(uint32_t*)(base + ((r1 >> 1) & 3) * 8 + (r1 >> 3) * 4) = *(uint32_t*)&h1;
        }
        const float4* w4 = (const float4*)w_o;
        float4* ws4 = (float4*)wo_s;
        for (int i = tid; i < 64 * 32 / 4; i += 512) ws4[i] = w4[i];
        if (tid < 64) bo_s[tid] = b_o[tid];
    }
    __syncthreads();

    float rs_lo = 0.f, rs_hi = 0.f;
    float acc[4][4];
    #pragma unroll
    for (int nt = 0; nt < 4; nt++)
        #pragma unroll
        for (int r = 0; r < 4; r++) acc[nt][r] = 0.f;

    // induction pointers (all other offsets are immediates)
    const char* pPhi = smp + OFF_PHI + g * 32 + tg * 8;
    const char* pG   = smp + OFF_G + g * GS3 + tg * 8;

    // ---- 64 units of 16 keys: full K per warp ----
    #pragma unroll 1
    for (int u = 0; u < 64; u++) {
        uint2 p0 = *(const uint2*)(pPhi);
        uint2 p1 = *(const uint2*)(pPhi + 256);
        uint2 g0 = *(const uint2*)(pG);
        uint2 g1 = *(const uint2*)(pG + 8 * GS3);
        uint2 g2 = *(const uint2*)(pG + 16 * GS3);
        uint2 g3 = *(const uint2*)(pG + 24 * GS3);
        pPhi += 512;
        pG   += 32;

        float e0 = 0.f, e1 = 0.f, e2 = 0.f, e3 = 0.f;
        mma1688_tf32(e0, e1, e2, e3, ta0, ta1, ta2, ta3, p0.x, p0.y);
        float f0 = 0.f, f1 = 0.f, f2 = 0.f, f3 = 0.f;
        mma1688_tf32(f0, f1, f2, f3, ta0, ta1, ta2, ta3, p1.x, p1.y);

        e0 = ex2f(e0); e1 = ex2f(e1); e2 = ex2f(e2); e3 = ex2f(e3);
        f0 = ex2f(f0); f1 = ex2f(f1); f2 = ex2f(f2); f3 = ex2f(f3);
        rs_lo += (e0 + e1) + (f0 + f1);
        rs_hi += (e2 + e3) + (f2 + f3);

        uint32_t a0 = bf16x2_of(e0, e1);
        uint32_t a1 = bf16x2_of(e2, e3);
        uint32_t a2 = bf16x2_of(f0, f1);
        uint32_t a3 = bf16x2_of(f2, f3);

        mma16816(acc[0][0], acc[0][1], acc[0][2], acc[0][3], a0, a1, a2, a3, g0.x, g0.y);
        mma16816(acc[1][0], acc[1][1], acc[1][2], acc[1][3], a0, a1, a2, a3, g1.x, g1.y);
        mma16816(acc[2][0], acc[2][1], acc[2][2], acc[2][3], a0, a1, a2, a3, g2.x, g2.y);
        mma16816(acc[3][0], acc[3][1], acc[3][2], acc[3][3], a0, a1, a2, a3, g3.x, g3.y);
    }

    // ---- complete rowsums via quad shuffle (warp covers ALL keys) ----
    rs_lo += __shfl_xor_sync(0xffffffffu, rs_lo, 1);
    rs_lo += __shfl_xor_sync(0xffffffffu, rs_lo, 2);
    rs_hi += __shfl_xor_sync(0xffffffffu, rs_hi, 1);
    rs_hi += __shfl_xor_sync(0xffffffffu, rs_hi, 2);
    float inv_lo = 1.f / rs_lo;
    float inv_hi = 1.f / rs_hi;

    __syncthreads();   // all warps done reading G/PHI -> AG alias safe

    // normalize in registers, stage AG[q][c]
    #pragma unroll
    for (int nt = 0; nt < 4; nt++) {
        int c0 = nt * 8 + 2 * tg;
        ag_s[(q0 + g) * 36 + c0]         = acc[nt][0] * inv_lo;
        ag_s[(q0 + g) * 36 + c0 + 1]     = acc[nt][1] * inv_lo;
        ag_s[(q0 + g + 8) * 36 + c0]     = acc[nt][2] * inv_hi;
        ag_s[(q0 + g + 8) * 36 + c0 + 1] = acc[nt][3] * inv_hi;
    }
    __syncthreads();

    // ---- projection + residual epilogue (coalesced) ----
    float sig = sigma[0];
    int nl = tid & 255;      // query within 256-tile
    int kh = tid >> 8;       // 0..1, 32 channels each

    float ag[32];
    #pragma unroll
    for (int c4 = 0; c4 < 8; c4++) {
        float4 v = *(const float4*)(ag_s + nl * 36 + 4 * c4);
        ag[4 * c4 + 0] = v.x; ag[4 * c4 + 1] = v.y;
        ag[4 * c4 + 2] = v.z; ag[4 * c4 + 3] = v.w;
    }
    size_t xoff_base = ((size_t)b * C_ + kh * 32) * N_ + qbase + nl;
    #pragma unroll 4
    for (int kk = 0; kk < 32; kk++) {
        int k = kh * 32 + kk;
        float val = bo_s[k];
        const float4* wrow = (const float4*)(wo_s + k * 32);
        #pragma unroll
        for (int c4 = 0; c4 < 8; c4++) {
            float4 w4 = wrow[c4];
            val += w4.x * ag[4 * c4] + w4.y * ag[4 * c4 + 1]
                 + w4.z * ag[4 * c4 + 2] + w4.w * ag[4 * c4 + 3];
        }
        size_t off = xoff_base + (size_t)kk * N_;
        out[off] = x[off] + sig * val;
    }
}

// ---------------------------------------------------------------------------
extern "C" void kernel_launch(void* const* d_in, const int* in_sizes, int n_in,
                              void* d_out, int out_size)
{
    const float* x       = (const float*)d_in[0];
    const float* w_theta = (const float*)d_in[1];
    const float* b_theta = (const float*)d_in[2];
    const float* w_phi   = (const float*)d_in[3];
    const float* b_phi   = (const float*)d_in[4];
    const float* w_g     = (const float*)d_in[5];
    const float* b_g     = (const float*)d_in[6];
    const float* w_o     = (const float*)d_in[7];
    const float* b_o     = (const float*)d_in[8];
    const float* sigma   = (const float*)d_in[9];
    float* out = (float*)d_out;

    convpool_kernel<<<dim3(B_ * 1024 / 256, 2), 256>>>(x, w_theta, b_theta,
                                                       w_phi, b_phi, w_g, b_g);

    cudaFuncSetAttribute(attn_main_kernel,
                         cudaFuncAttributeMaxDynamicSharedMemorySize, SMEM_REQ);
    attn_main_kernel<<<dim3(N_ / 256, B_), 512, SMEM_REQ>>>(x, w_o, b_o, sigma, out);
}

// round 13
// speedup vs baseline: 1.2494x; 1.0963x over previous
#include <cuda_runtime.h>
#include <cuda_bf16.h>
#include <cstdint>

#define B_   16
#define C_   64
#define H_   64
#define W_   64
#define N_   4096
#define M_   1024
#define D8   8
#define D2   32
#define CH48 48

// Device scratch (no cudaMalloc allowed)
__device__ float    d_tmp[B_ * CH48 * N_];       // theta (ch 0..7) full-res
__device__ uint32_t d_phip[B_ * M_ * 8];         // phi pre-packed tf32 frag slots
__device__ uint32_t d_gp[B_ * D2 * M_ / 2];      // g pre-packed bf16x2 frag slots

// ---- f32x2 packed helpers ---------------------------------------------------
__device__ __forceinline__ void ffma2(unsigned long long& d,
                                      unsigned long long a,
                                      unsigned long long b) {
    asm("fma.rn.f32x2 %0, %1, %2, %0;" : "+l"(d) : "l"(a), "l"(b));
}
__device__ __forceinline__ unsigned long long pack_ff(float lo, float hi) {
    unsigned long long r;
    asm("mov.b64 %0, {%1,%2};" : "=l"(r) : "f"(lo), "f"(hi));
    return r;
}
__device__ __forceinline__ void unpack_ff(unsigned long long v, float& lo, float& hi) {
    asm("mov.b64 {%0,%1}, %2;" : "=f"(lo), "=f"(hi) : "l"(v));
}

// ---- mma wrappers (baseline PTX, legal on plain sm_103) ----------------------
__device__ __forceinline__ void mma16816(float& d0, float& d1, float& d2, float& d3,
                                         uint32_t a0, uint32_t a1, uint32_t a2, uint32_t a3,
                                         uint32_t b0, uint32_t b1) {
    asm volatile(
        "mma.sync.aligned.m16n8k16.row.col.f32.bf16.bf16.f32 "
        "{%0,%1,%2,%3}, {%4,%5,%6,%7}, {%8,%9}, {%0,%1,%2,%3};"
        : "+f"(d0), "+f"(d1), "+f"(d2), "+f"(d3)
        : "r"(a0), "r"(a1), "r"(a2), "r"(a3), "r"(b0), "r"(b1));
}
__device__ __forceinline__ void mma1688_tf32(float& d0, float& d1, float& d2, float& d3,
                                             uint32_t a0, uint32_t a1, uint32_t a2, uint32_t a3,
                                             uint32_t b0, uint32_t b1) {
    asm volatile(
        "mma.sync.aligned.m16n8k8.row.col.f32.tf32.tf32.f32 "
        "{%0,%1,%2,%3}, {%4,%5,%6,%7}, {%8,%9}, {%0,%1,%2,%3};"
        : "+f"(d0), "+f"(d1), "+f"(d2), "+f"(d3)
        : "r"(a0), "r"(a1), "r"(a2), "r"(a3), "r"(b0), "r"(b1));
}
__device__ __forceinline__ uint32_t to_tf32(float v) {
    uint32_t r;
    asm("cvt.rna.tf32.f32 %0, %1;" : "=r"(r) : "f"(v));
    return r;
}
__device__ __forceinline__ uint32_t bf16x2_of(float lo, float hi) {
    uint32_t r;
    asm("cvt.rn.bf16x2.f32 %0, %1, %2;" : "=r"(r) : "f"(hi), "f"(lo));
    return r;
}
__device__ __forceinline__ float ex2f(float v) {
    float r;
    asm("ex2.approx.f32 %0, %1;" : "=f"(r) : "f"(v));
    return r;
}

// ---------------------------------------------------------------------------
// P1: FUSED conv1x1 + 2x2 maxpool + FRAG PACKING.
// phi/g are written to gmem already in the main kernel's smem frag layouts
// (tf32 u32 slots / bf16x2 pair slots), so the main kernel setup is a memcpy.
// Lanes are adjacent in m, so the (m, m+1) bf16 pairing is one shfl_down.
// ---------------------------------------------------------------------------
__global__ void __launch_bounds__(256) convpool_kernel(
    const float* __restrict__ x,
    const float* __restrict__ w_theta, const float* __restrict__ b_theta,
    const float* __restrict__ w_phi,   const float* __restrict__ b_phi,
    const float* __restrict__ w_g,     const float* __restrict__ b_g)
{
    __shared__ float w_s[C_ * 24];
    __shared__ float bias_s[24];
    int tid    = threadIdx.x;
    int chbase = blockIdx.y * 24;

    for (int i = tid; i < C_ * 24; i += 256) {
        int c = i / 24, chp = i % 24;
        int ch = chbase + chp;
        float v;
        if (ch < 8)       v = w_theta[ch * C_ + c];
        else if (ch < 16) v = w_phi[(ch - 8) * C_ + c];
        else              v = w_g[(ch - 16) * C_ + c];
        w_s[i] = v;
    }
    if (tid < 24) {
        int ch = chbase + tid;
        bias_s[tid] = (ch < 8) ? b_theta[ch]
                    : (ch < 16 ? b_phi[ch - 8] : b_g[ch - 16]);
    }
    __syncthreads();

    int idx = blockIdx.x * 256 + tid;
    int b  = idx >> 10;
    int q  = idx & 1023;           // q == m (pooled index), consecutive in tid
    int mh = q >> 5, mw = q & 31;
    int n00 = (2 * mh) * W_ + 2 * mw;

    unsigned long long accR0[24], accR1[24];
    #pragma unroll
    for (int j = 0; j < 24; j++) {
        unsigned long long bb = pack_ff(bias_s[j], bias_s[j]);
        accR0[j] = bb; accR1[j] = bb;
    }

    const float* xb = x + ((size_t)b * C_) * N_ + n00;
    #pragma unroll 4
    for (int c = 0; c < C_; c++) {
        unsigned long long x0 = *(const unsigned long long*)(xb + (size_t)c * N_);
        unsigned long long x1 = *(const unsigned long long*)(xb + (size_t)c * N_ + W_);
        const float* wrow = w_s + c * 24;
        #pragma unroll
        for (int j = 0; j < 24; j++) {
            float wj = wrow[j];
            unsigned long long w2 = pack_ff(wj, wj);
            ffma2(accR0[j], x0, w2);
            ffma2(accR1[j], x1, w2);
        }
    }

    int m = q;
    int r = m & 15;
    // g pair-slot byte offset within a channel row (2048 B per channel)
    uint32_t gslot = (uint32_t)((m & ~15) * 2 + ((r >> 1) & 3) * 8 + (r >> 3) * 4);
    bool even = (m & 1) == 0;

    if (chbase == 0) {
        // theta: store all 4 positions (full res)
        float* tb = d_tmp + (size_t)b * CH48 * N_ + n00;
        #pragma unroll
        for (int ch = 0; ch < 8; ch++) {
            *(unsigned long long*)(tb + (size_t)ch * N_)      = accR0[ch];
            *(unsigned long long*)(tb + (size_t)ch * N_ + W_) = accR1[ch];
        }
        // phi ch8-15: maxpool -> tf32 packed slot
        #pragma unroll
        for (int ch = 8; ch < 16; ch++) {
            float a0, a1, b0, b1;
            unpack_ff(accR0[ch], a0, a1);
            unpack_ff(accR1[ch], b0, b1);
            float v = fmaxf(fmaxf(a0, a1), fmaxf(b0, b1));
            int d = ch - 8;
            d_phip[b * 8192 + m * 8 + (d & 3) * 2 + (d >> 2)] = to_tf32(v);
        }
        // g ch0-7: maxpool -> bf16x2 pair slot (shuffle neighbor m+1)
        #pragma unroll
        for (int ch = 16; ch < 24; ch++) {
            float a0, a1, b0, b1;
            unpack_ff(accR0[ch], a0, a1);
            unpack_ff(accR1[ch], b0, b1);
            float v = fmaxf(fmaxf(a0, a1), fmaxf(b0, b1));
            float v1 = __shfl_down_sync(0xffffffffu, v, 1);
            if (even) {
                __nv_bfloat162 h = __floats2bfloat162_rn(v, v1);
                uint32_t byte = (uint32_t)(b * 32 + (ch - 16)) * 2048 + gslot;
                d_gp[byte >> 2] = *(uint32_t*)&h;
            }
        }
    } else {
        // g ch8-31
        #pragma unroll
        for (int chp = 0; chp < 24; chp++) {
            float a0, a1, b0, b1;
            unpack_ff(accR0[chp], a0, a1);
            unpack_ff(accR1[chp], b0, b1);
            float v = fmaxf(fmaxf(a0, a1), fmaxf(b0, b1));
            float v1 = __shfl_down_sync(0xffffffffu, v, 1);
            if (even) {
                __nv_bfloat162 h = __floats2bfloat162_rn(v, v1);
                uint32_t byte = (uint32_t)(b * 32 + 8 + chp) * 2048 + gslot;
                d_gp[byte >> 2] = *(uint32_t*)&h;
            }
        }
    }
}

// ---------------------------------------------------------------------------
// Main kernel (R12 winner): setup is now a pure 16B-chunk memcpy.
// Loop body, layouts, numerics identical to R12.
// ---------------------------------------------------------------------------
#define GS3    2080                         // smem g row stride bytes
#define OFF_G    0                          // 32*2080 = 66560
#define OFF_PHI  66560                      // 32768 -> 99328
#define OFF_WO   99328                      // 8192  -> 107520
#define OFF_BO   107520                     // 256   -> 107776
#define OFF_AG   0                          // alias G (dead after loop)
#define SMEM_REQ 107776

__global__ void __launch_bounds__(512, 2) attn_main_kernel(
    const float* __restrict__ x,
    const float* __restrict__ w_o,
    const float* __restrict__ b_o,
    const float* __restrict__ sigma,
    float* __restrict__ out)
{
    extern __shared__ char smp[];
    float* wo_s = (float*)(smp + OFF_WO);
    float* bo_s = (float*)(smp + OFF_BO);
    float* ag_s = (float*)(smp + OFF_AG);

    int tid   = threadIdx.x;
    int warp  = tid >> 5, lane = tid & 31;
    int b     = blockIdx.y;
    int qbase = blockIdx.x * 256;

    int q0 = warp * 16;
    int g  = lane >> 2;
    int tg = lane & 3;

    // theta A-fragments straight from gmem (prescaled by log2e)
    const float* tsrc = d_tmp + (size_t)b * CH48 * N_ + qbase;
    const float sc = 1.4426950408889634f;
    uint32_t ta0 = to_tf32(tsrc[(size_t)tg * N_ + q0 + g] * sc);
    uint32_t ta1 = to_tf32(tsrc[(size_t)tg * N_ + q0 + g + 8] * sc);
    uint32_t ta2 = to_tf32(tsrc[(size_t)(tg + 4) * N_ + q0 + g] * sc);
    uint32_t ta3 = to_tf32(tsrc[(size_t)(tg + 4) * N_ + q0 + g + 8] * sc);

    // ---- setup: pure memcpy of pre-packed frag data ----
    {
        const uint4* gp = (const uint4*)(d_gp + (size_t)b * 16384);
        for (int i = tid; i < 4096; i += 512) {       // 65536 B
            int c = i >> 7, w = i & 127;
            *(uint4*)(smp + OFF_G + c * GS3 + w * 16) = gp[i];
        }
        const uint4* pp = (const uint4*)(d_phip + (size_t)b * 8192);
        for (int i = tid; i < 2048; i += 512)         // 32768 B
            *(uint4*)(smp + OFF_PHI + i * 16) = pp[i];
        const float4* w4 = (const float4*)w_o;
        float4* ws4 = (float4*)wo_s;
        for (int i = tid; i < 64 * 32 / 4; i += 512) ws4[i] = w4[i];
        if (tid < 64) bo_s[tid] = b_o[tid];
    }
    __syncthreads();

    float rs_lo = 0.f, rs_hi = 0.f;
    float acc[4][4];
    #pragma unroll
    for (int nt = 0; nt < 4; nt++)
        #pragma unroll
        for (int r = 0; r < 4; r++) acc[nt][r] = 0.f;

    // induction pointers (all other offsets are immediates)
    const char* pPhi = smp + OFF_PHI + g * 32 + tg * 8;
    const char* pG   = smp + OFF_G + g * GS3 + tg * 8;

    // ---- 64 units of 16 keys: full K per warp ----
    #pragma unroll 1
    for (int u = 0; u < 64; u++) {
        uint2 p0 = *(const uint2*)(pPhi);
        uint2 p1 = *(const uint2*)(pPhi + 256);
        uint2 g0 = *(const uint2*)(pG);
        uint2 g1 = *(const uint2*)(pG + 8 * GS3);
        uint2 g2 = *(const uint2*)(pG + 16 * GS3);
        uint2 g3 = *(const uint2*)(pG + 24 * GS3);
        pPhi += 512;
        pG   += 32;

        float e0 = 0.f, e1 = 0.f, e2 = 0.f, e3 = 0.f;
        mma1688_tf32(e0, e1, e2, e3, ta0, ta1, ta2, ta3, p0.x, p0.y);
        float f0 = 0.f, f1 = 0.f, f2 = 0.f, f3 = 0.f;
        mma1688_tf32(f0, f1, f2, f3, ta0, ta1, ta2, ta3, p1.x, p1.y);

        e0 = ex2f(e0); e1 = ex2f(e1); e2 = ex2f(e2); e3 = ex2f(e3);
        f0 = ex2f(f0); f1 = ex2f(f1); f2 = ex2f(f2); f3 = ex2f(f3);
        rs_lo += (e0 + e1) + (f0 + f1);
        rs_hi += (e2 + e3) + (f2 + f3);

        uint32_t a0 = bf16x2_of(e0, e1);
        uint32_t a1 = bf16x2_of(e2, e3);
        uint32_t a2 = bf16x2_of(f0, f1);
        uint32_t a3 = bf16x2_of(f2, f3);

        mma16816(acc[0][0], acc[0][1], acc[0][2], acc[0][3], a0, a1, a2, a3, g0.x, g0.y);
        mma16816(acc[1][0], acc[1][1], acc[1][2], acc[1][3], a0, a1, a2, a3, g1.x, g1.y);
        mma16816(acc[2][0], acc[2][1], acc[2][2], acc[2][3], a0, a1, a2, a3, g2.x, g2.y);
        mma16816(acc[3][0], acc[3][1], acc[3][2], acc[3][3], a0, a1, a2, a3, g3.x, g3.y);
    }

    // ---- complete rowsums via quad shuffle ----
    rs_lo += __shfl_xor_sync(0xffffffffu, rs_lo, 1);
    rs_lo += __shfl_xor_sync(0xffffffffu, rs_lo, 2);
    rs_hi += __shfl_xor_sync(0xffffffffu, rs_hi, 1);
    rs_hi += __shfl_xor_sync(0xffffffffu, rs_hi, 2);
    float inv_lo = 1.f / rs_lo;
    float inv_hi = 1.f / rs_hi;

    __syncthreads();   // all warps done reading G/PHI -> AG alias safe

    // normalize in registers, stage AG[q][c]
    #pragma unroll
    for (int nt = 0; nt < 4; nt++) {
        int c0 = nt * 8 + 2 * tg;
        ag_s[(q0 + g) * 36 + c0]         = acc[nt][0] * inv_lo;
        ag_s[(q0 + g) * 36 + c0 + 1]     = acc[nt][1] * inv_lo;
        ag_s[(q0 + g + 8) * 36 + c0]     = acc[nt][2] * inv_hi;
        ag_s[(q0 + g + 8) * 36 + c0 + 1] = acc[nt][3] * inv_hi;
    }
    __syncthreads();

    // ---- projection + residual epilogue (coalesced) ----
    float sig = sigma[0];
    int nl = tid & 255;
    int kh = tid >> 8;

    float ag[32];
    #pragma unroll
    for (int c4 = 0; c4 < 8; c4++) {
        float4 v = *(const float4*)(ag_s + nl * 36 + 4 * c4);
        ag[4 * c4 + 0] = v.x; ag[4 * c4 + 1] = v.y;
        ag[4 * c4 + 2] = v.z; ag[4 * c4 + 3] = v.w;
    }
    size_t xoff_base = ((size_t)b * C_ + kh * 32) * N_ + qbase + nl;
    #pragma unroll 4
    for (int kk = 0; kk < 32; kk++) {
        int k = kh * 32 + kk;
        float val = bo_s[k];
        const float4* wrow = (const float4*)(wo_s + k * 32);
        #pragma unroll
        for (int c4 = 0; c4 < 8; c4++) {
            float4 w4 = wrow[c4];
            val += w4.x * ag[4 * c4] + w4.y * ag[4 * c4 + 1]
                 + w4.z * ag[4 * c4 + 2] + w4.w * ag[4 * c4 + 3];
        }
        size_t off = xoff_base + (size_t)kk * N_;
        out[off] = x[off] + sig * val;
    }
}

// ---------------------------------------------------------------------------
extern "C" void kernel_launch(void* const* d_in, const int* in_sizes, int n_in,
                              void* d_out, int out_size)
{
    const float* x       = (const float*)d_in[0];
    const float* w_theta = (const float*)d_in[1];
    const float* b_theta = (const float*)d_in[2];
    const float* w_phi   = (const float*)d_in[3];
    const float* b_phi   = (const float*)d_in[4];
    const float* w_g     = (const float*)d_in[5];
    const float* b_g     = (const float*)d_in[6];
    const float* w_o     = (const float*)d_in[7];
    const float* b_o     = (const float*)d_in[8];
    const float* sigma   = (const float*)d_in[9];
    float* out = (float*)d_out;

    convpool_kernel<<<dim3(B_ * 1024 / 256, 2), 256>>>(x, w_theta, b_theta,
                                                       w_phi, b_phi, w_g, b_g);

    cudaFuncSetAttribute(attn_main_kernel,
                         cudaFuncAttributeMaxDynamicSharedMemorySize, SMEM_REQ);
    attn_main_kernel<<<dim3(N_ / 256, B_), 512, SMEM_REQ>>>(x, w_o, b_o, sigma, out);
}